// round 1
// baseline (speedup 1.0000x reference)
#include <cuda_runtime.h>
#include <cuda_bf16.h>

// SiLU: out = x * sigmoid(x), elementwise over 4*4096*4096 fp32.
// Pure HBM-streaming kernel: float4 vectorized, grid-stride.

__device__ __forceinline__ float silu_f(float x) {
    // sigmoid via fast exp; fp32 precision vastly exceeds 1e-3 rel-err gate
    return x * (1.0f / (1.0f + __expf(-x)));
}

__global__ void __launch_bounds__(256) silu_vec4_kernel(
    const float4* __restrict__ in, float4* __restrict__ out, long long n4)
{
    long long i = (long long)blockIdx.x * blockDim.x + threadIdx.x;
    long long stride = (long long)gridDim.x * blockDim.x;
    for (; i < n4; i += stride) {
        float4 v = in[i];
        float4 r;
        r.x = silu_f(v.x);
        r.y = silu_f(v.y);
        r.z = silu_f(v.z);
        r.w = silu_f(v.w);
        out[i] = r;
    }
}

__global__ void silu_tail_kernel(
    const float* __restrict__ in, float* __restrict__ out,
    long long start, long long n)
{
    long long i = start + blockIdx.x * blockDim.x + threadIdx.x;
    if (i < n) out[i] = silu_f(in[i]);
}

extern "C" void kernel_launch(void* const* d_in, const int* in_sizes, int n_in,
                              void* d_out, int out_size) {
    const float* x = (const float*)d_in[0];
    float* out = (float*)d_out;
    long long n = (long long)in_sizes[0];   // 67,108,864

    long long n4 = n / 4;
    int threads = 256;
    // Deep grid: plenty of CTAs per SM for memory-latency hiding.
    long long blocks64 = (n4 + threads - 1) / threads;
    int blocks = (int)(blocks64 > 1048576 ? 1048576 : blocks64);
    if (blocks < 1) blocks = 1;

    silu_vec4_kernel<<<blocks, threads>>>(
        (const float4*)x, (float4*)out, n4);

    long long rem = n - n4 * 4;
    if (rem > 0) {
        int tb = (int)((rem + 255) / 256);
        silu_tail_kernel<<<tb, 256>>>(x, out, n4 * 4, n);
    }
}

// round 2
// speedup vs baseline: 1.1862x; 1.1862x over previous
#include <cuda_runtime.h>
#include <cuda_bf16.h>

// SiLU: out = x * sigmoid(x), 4*4096*4096 fp32. Pure HBM stream.
// R2: 32-bit indexing, 4x float4 per thread (MLP=4), streaming ld/st hints.

constexpr int THREADS = 256;
constexpr int UNROLL  = 4;                       // float4s per thread
constexpr int TILE    = THREADS * UNROLL;        // float4s per block

__device__ __forceinline__ float silu_f(float x) {
    return x * (1.0f / (1.0f + __expf(-x)));
}

__device__ __forceinline__ float4 silu_v(float4 v) {
    float4 r;
    r.x = silu_f(v.x);
    r.y = silu_f(v.y);
    r.z = silu_f(v.z);
    r.w = silu_f(v.w);
    return r;
}

__global__ void __launch_bounds__(THREADS) silu_vec4_mlp4_kernel(
    const float4* __restrict__ in, float4* __restrict__ out, int n4)
{
    int base = blockIdx.x * TILE + threadIdx.x;

    if (base + (UNROLL - 1) * THREADS < n4) {
        // Fast path: full tile. Front-batch all loads for MLP=4.
        float4 v[UNROLL];
#pragma unroll
        for (int k = 0; k < UNROLL; k++)
            v[k] = __ldcs(&in[base + k * THREADS]);
#pragma unroll
        for (int k = 0; k < UNROLL; k++)
            __stcs(&out[base + k * THREADS], silu_v(v[k]));
    } else {
        // Edge tile
#pragma unroll
        for (int k = 0; k < UNROLL; k++) {
            int i = base + k * THREADS;
            if (i < n4) __stcs(&out[i], silu_v(__ldcs(&in[i])));
        }
    }
}

__global__ void silu_tail_kernel(
    const float* __restrict__ in, float* __restrict__ out, int start, int n)
{
    int i = start + blockIdx.x * blockDim.x + threadIdx.x;
    if (i < n) out[i] = silu_f(in[i]);
}

extern "C" void kernel_launch(void* const* d_in, const int* in_sizes, int n_in,
                              void* d_out, int out_size) {
    const float* x = (const float*)d_in[0];
    float* out = (float*)d_out;
    int n = in_sizes[0];                 // 67,108,864 (< 2^31)

    int n4 = n / 4;                      // 16,777,216
    int blocks = (n4 + TILE - 1) / TILE; // 16,384

    silu_vec4_mlp4_kernel<<<blocks, THREADS>>>(
        (const float4*)x, (float4*)out, n4);

    int rem = n - n4 * 4;
    if (rem > 0) {
        int tb = (rem + 255) / 256;
        silu_tail_kernel<<<tb, 256>>>(x, out, n4 * 4, n);
    }
}